// round 3
// baseline (speedup 1.0000x reference)
#include <cuda_runtime.h>
#include <cstdint>

// Problem constants (fixed shapes for this problem)
#define NNODES 8192
#define KDIM   256     // in_embedding_len
#define MOUT   128     // out_embedding_len
#define EPSV   1e-5f
#define MASK_WORDS_PER_ROW (NNODES / 32)   // 256
#define MAX_DEG 2048

// Scratch (no cudaMalloc allowed): intermediates + adjacency bitmask
__device__ float    g_h1[NNODES * KDIM];
__device__ float    g_h2[NNODES * KDIM];
__device__ unsigned g_mask[NNODES * MASK_WORDS_PER_ROW];   // 8 MB

// ---------------- packed f32x2 helpers (Blackwell FFMA2 path) ----------------
__device__ __forceinline__ unsigned long long pk2(float lo, float hi) {
    unsigned long long r;
    asm("mov.b64 %0, {%1, %2};" : "=l"(r) : "f"(lo), "f"(hi));
    return r;
}
__device__ __forceinline__ void upk2(unsigned long long v, float& lo, float& hi) {
    asm("mov.b64 {%0, %1}, %2;" : "=f"(lo), "=f"(hi) : "l"(v));
}
__device__ __forceinline__ unsigned long long fma2(unsigned long long a,
                                                   unsigned long long b,
                                                   unsigned long long c) {
    unsigned long long d;
    asm("fma.rn.f32x2 %0, %1, %2, %3;" : "=l"(d) : "l"(a), "l"(b), "l"(c));
    return d;
}

// ---------------- fused GEMM + bias + LayerNorm (+tanh) ----------------
// out[row, :] = maybe_tanh( LN( X[row,:] @ W + bias ) * gam + bet )
// X: [NNODES, 256], W: [256, M], M in {256, 128}. One block = 64 rows x M cols.
// Thread layout: 256 threads; warp ty (=t/32) owns rows ty*8..ty*8+7 entirely,
// lane tx owns cols tx*CPT..tx*CPT+CPT-1 -> LayerNorm is a pure warp shfl reduce.
template <int M, bool DO_TANH>
__device__ __forceinline__
void gemm_ln_body(const float* __restrict__ X, const float* __restrict__ W,
                  const float* __restrict__ bias, const float* __restrict__ gam,
                  const float* __restrict__ bet, float* __restrict__ out)
{
    constexpr int K   = 256;
    constexpr int BM  = 64;
    constexpr int BK  = 32;
    constexpr int CPT = M / 32;      // cols per thread: 8 (M=256) or 4 (M=128)
    constexpr int CP2 = CPT / 2;     // packed f32x2 accumulators per row

    __shared__ float Xs[BK][BM + 4];     // stride 68: float4-aligned rows
    __shared__ float Ws[BK][M];          // contiguous, same layout as gmem tile

    const int t   = threadIdx.x;
    const int tx  = t & 31;
    const int ty  = t >> 5;
    const int row0 = blockIdx.x * BM;

    unsigned long long acc[8][CP2];
#pragma unroll
    for (int i = 0; i < 8; i++)
#pragma unroll
        for (int j = 0; j < CP2; j++) acc[i][j] = 0ull;   // (0.0f, 0.0f)

    for (int k0 = 0; k0 < K; k0 += BK) {
        // X tile 64x32: global-coalesced, stored transposed
#pragma unroll
        for (int i = 0; i < (BM * BK) / 256; i++) {
            int l  = t + i * 256;
            int r  = l >> 5;
            int kk = l & 31;
            Xs[kk][r] = X[(row0 + r) * K + k0 + kk];
        }
        // W tile 32xM: contiguous block -> vectorized copy
        {
            const float4* src = reinterpret_cast<const float4*>(W + k0 * M);
            float4*       dst = reinterpret_cast<float4*>(&Ws[0][0]);
#pragma unroll
            for (int i = 0; i < (BK * M) / (4 * 256); i++)
                dst[t + i * 256] = src[t + i * 256];
        }
        __syncthreads();

#pragma unroll
        for (int kk = 0; kk < BK; ++kk) {
            float4 a0 = *reinterpret_cast<const float4*>(&Xs[kk][ty * 8]);
            float4 a1 = *reinterpret_cast<const float4*>(&Xs[kk][ty * 8 + 4]);
            float av[8] = {a0.x, a0.y, a0.z, a0.w, a1.x, a1.y, a1.z, a1.w};
            unsigned long long bp[CP2];
#pragma unroll
            for (int j = 0; j < CP2; j += 2) {
                float4 b4 = *reinterpret_cast<const float4*>(&Ws[kk][tx * CPT + j * 2]);
                bp[j]     = pk2(b4.x, b4.y);
                bp[j + 1] = pk2(b4.z, b4.w);
            }
#pragma unroll
            for (int ri = 0; ri < 8; ri++) {
                unsigned long long aa = pk2(av[ri], av[ri]);
#pragma unroll
                for (int j = 0; j < CP2; j++) acc[ri][j] = fma2(aa, bp[j], acc[ri][j]);
            }
        }
        __syncthreads();
    }

    // Per-thread column params
    const int cbase = tx * CPT;
    float bs[CPT], gs[CPT], bes[CPT];
#pragma unroll
    for (int c = 0; c < CPT; c++) {
        bs[c]  = bias[cbase + c];
        gs[c]  = gam[cbase + c];
        bes[c] = bet[cbase + c];
    }

    // LayerNorm (+tanh) epilogue: warp ty reduces each of its 8 rows
#pragma unroll
    for (int ri = 0; ri < 8; ri++) {
        float v[CPT];
#pragma unroll
        for (int j = 0; j < CP2; j++) upk2(acc[ri][j], v[2 * j], v[2 * j + 1]);
        float s = 0.f, ss = 0.f;
#pragma unroll
        for (int c = 0; c < CPT; c++) {
            v[c] += bs[c];
            s  += v[c];
            ss += v[c] * v[c];
        }
#pragma unroll
        for (int o = 16; o > 0; o >>= 1) {
            s  += __shfl_xor_sync(0xffffffffu, s, o);
            ss += __shfl_xor_sync(0xffffffffu, ss, o);
        }
        const float mu   = s * (1.0f / M);
        const float var  = ss * (1.0f / M) - mu * mu;
        const float rstd = rsqrtf(var + EPSV);
        const int   row  = row0 + ty * 8 + ri;

        float ov[CPT];
#pragma unroll
        for (int c = 0; c < CPT; c++) {
            float o = (v[c] - mu) * rstd * gs[c] + bes[c];
            if (DO_TANH) o = tanhf(o);
            ov[c] = o;
        }
        float4* op = reinterpret_cast<float4*>(&out[row * M + cbase]);
#pragma unroll
        for (int j = 0; j < CPT / 4; j++)
            op[j] = make_float4(ov[4 * j], ov[4 * j + 1], ov[4 * j + 2], ov[4 * j + 3]);
    }
}

// Wrappers referencing device globals directly (no cudaGetSymbolAddress needed)
__global__ __launch_bounds__(256, 1)
void gemm_ln_l1(const float* __restrict__ X, const float* __restrict__ W,
                const float* __restrict__ b, const float* __restrict__ g,
                const float* __restrict__ be)
{
    gemm_ln_body<256, true>(X, W, b, g, be, g_h1);
}
__global__ __launch_bounds__(256, 1)
void gemm_ln_l2(const float* __restrict__ W, const float* __restrict__ b,
                const float* __restrict__ g, const float* __restrict__ be)
{
    gemm_ln_body<256, true>(g_h1, W, b, g, be, g_h2);
}
__global__ __launch_bounds__(256, 1)
void gemm_ln_l3(const float* __restrict__ W, const float* __restrict__ b,
                const float* __restrict__ g, const float* __restrict__ be,
                float* __restrict__ emb)
{
    gemm_ln_body<128, false>(g_h2, W, b, g, be, emb);
}

// ---------------- adjacency bitmask ----------------
__global__ void zero_mask_kernel() {
    int i = blockIdx.x * blockDim.x + threadIdx.x;   // 2048*256 = 524288 uint4
    reinterpret_cast<uint4*>(g_mask)[i] = make_uint4(0u, 0u, 0u, 0u);
}

__global__ void set_edges_kernel(const int* __restrict__ ei, int E) {
    int e = blockIdx.x * blockDim.x + threadIdx.x;
    if (e >= E) return;
    int s = ei[e] - 1;         // 1-indexed input
    int d = ei[E + e] - 1;
    atomicOr(&g_mask[(unsigned)(s * NNODES + d) >> 5], 1u << (d & 31));
    atomicOr(&g_mask[(unsigned)(d * NNODES + s) >> 5], 1u << (s & 31));
}

// ---------------- sparse GAT row kernel ----------------
// One block per node i (128 threads).
//  1) scan the 256-word bitmask row -> compact neighbor list (dedup'd by construction)
//  2) warp-per-neighbor dot(emb_i, emb_j), exp -> s_j
//  3) block-reduce den = sum s_j
//  4) thread d accumulates x_gat[i][d] = (1/den) * sum_j s_j * emb_j[d]  (coalesced)
__global__ __launch_bounds__(128)
void gat_row_kernel(const float* __restrict__ emb, float* __restrict__ xgat)
{
    const int i    = blockIdx.x;
    const int t    = threadIdx.x;
    const int lane = t & 31;
    const int wid  = t >> 5;

    __shared__ float ei_s[MOUT];
    __shared__ int   nbr[MAX_DEG];
    __shared__ float sv[MAX_DEG];
    __shared__ int   cnt;
    __shared__ float wsum[4];

    ei_s[t] = emb[i * MOUT + t];
    if (t == 0) cnt = 0;
    __syncthreads();

    // 1) compact the set bits of mask row i
    const unsigned* row = &g_mask[i * MASK_WORDS_PER_ROW];
#pragma unroll
    for (int w = t; w < MASK_WORDS_PER_ROW; w += 128) {
        unsigned m = row[w];
        while (m) {
            int b = __ffs(m) - 1;
            m &= m - 1;
            int p = atomicAdd(&cnt, 1);
            if (p < MAX_DEG) nbr[p] = w * 32 + b;
        }
    }
    __syncthreads();
    const int deg = cnt < MAX_DEG ? cnt : MAX_DEG;

    // 2) scores: warp per neighbor
    for (int n = wid; n < deg; n += 4) {
        const float* ej = &emb[nbr[n] * MOUT];
        float d = ej[lane]       * ei_s[lane]
                + ej[lane + 32]  * ei_s[lane + 32]
                + ej[lane + 64]  * ei_s[lane + 64]
                + ej[lane + 96]  * ei_s[lane + 96];
#pragma unroll
        for (int o = 16; o > 0; o >>= 1) d += __shfl_xor_sync(0xffffffffu, d, o);
        if (lane == 0) sv[n] = expf(d);
    }
    __syncthreads();

    // 3) denominator
    float a = 0.f;
    for (int n = t; n < deg; n += 128) a += sv[n];
#pragma unroll
    for (int o = 16; o > 0; o >>= 1) a += __shfl_xor_sync(0xffffffffu, a, o);
    if (lane == 0) wsum[wid] = a;
    __syncthreads();
    const float den  = wsum[0] + wsum[1] + wsum[2] + wsum[3];
    const float invd = den > 0.f ? 1.0f / den : 0.0f;

    // 4) weighted aggregation: thread t owns output dim t (coalesced emb reads)
    float o0 = 0.f;
#pragma unroll 4
    for (int n = 0; n < deg; n++)
        o0 += sv[n] * __ldg(&emb[nbr[n] * MOUT + t]);

    xgat[i * MOUT + t] = o0 * invd;
}

// ---------------- launch ----------------
extern "C" void kernel_launch(void* const* d_in, const int* in_sizes, int n_in,
                              void* d_out, int out_size)
{
    const float* x   = (const float*)d_in[0];
    const int*   ei  = (const int*)d_in[1];
    const float* w1  = (const float*)d_in[2];
    const float* b1  = (const float*)d_in[3];
    const float* g1  = (const float*)d_in[4];
    const float* be1 = (const float*)d_in[5];
    const float* w2  = (const float*)d_in[6];
    const float* b2  = (const float*)d_in[7];
    const float* g2  = (const float*)d_in[8];
    const float* be2 = (const float*)d_in[9];
    const float* w3  = (const float*)d_in[10];
    const float* b3  = (const float*)d_in[11];
    const float* g3  = (const float*)d_in[12];
    const float* be3 = (const float*)d_in[13];

    float* out  = (float*)d_out;
    float* emb  = out;                     // [N, 128]
    float* xgat = out + NNODES * MOUT;     // [N, 128]

    const int E = in_sizes[1] / 2;

    // adjacency bitmask
    zero_mask_kernel<<<2048, 256>>>();
    set_edges_kernel<<<(E + 255) / 256, 256>>>(ei, E);

    // encoder (intermediates live in __device__ globals, referenced in-kernel)
    gemm_ln_l1<<<NNODES / 64, 256>>>(x,  w1, b1, g1, be1);
    gemm_ln_l2<<<NNODES / 64, 256>>>(w2, b2, g2, be2);
    gemm_ln_l3<<<NNODES / 64, 256>>>(w3, b3, g3, be3, emb);

    // sparse GAT
    gat_row_kernel<<<NNODES, 128>>>(emb, xgat);
}